// round 6
// baseline (speedup 1.0000x reference)
#include <cuda_runtime.h>

// Problem constants
#define N_TOK   9216        // H*W = 96*96
#define NBATCH  2
#define NC      64
#define NC8     8
#define QTILES  72          // 9216 / 128 query tiles
#define KTILE   64
#define NKT     144         // 9216 / 64 key tiles

// ---------------- scratch (static device allocation: allowed) ----------------
__device__ float g_sig_inv[3];
__device__ float g_fT[NBATCH * N_TOK * NC8];   // keys,    [b][n][8]
__device__ float g_gT[NBATCH * N_TOK * NC8];   // queries, [b][n][8]
__device__ float g_hT[NBATCH * N_TOK * NC];    // values,  [b][n][64]

// ---------------- packed f32x2 helpers (sm_100+: FFMA2 path) ----------------
__device__ __forceinline__ unsigned long long pk2(float a, float b) {
    unsigned long long r;
    asm("mov.b64 %0, {%1, %2};" : "=l"(r) : "f"(a), "f"(b));
    return r;
}
__device__ __forceinline__ void upk2(unsigned long long v, float& a, float& b) {
    asm("mov.b64 {%0, %1}, %2;" : "=f"(a), "=f"(b) : "l"(v));
}
__device__ __forceinline__ void fma2(unsigned long long& d,
                                     unsigned long long a, unsigned long long b) {
    asm("fma.rn.f32x2 %0, %1, %2, %0;" : "+l"(d) : "l"(a), "l"(b));
}
__device__ __forceinline__ void mul2(unsigned long long& d, unsigned long long s) {
    asm("mul.rn.f32x2 %0, %0, %1;" : "+l"(d) : "l"(s));
}

// =============================================================================
// Kernel 1: spectral norms via trace-normalized repeated squaring.
// P_0 = W W^T; P_{k+1} = (P_k / t_k)^2, t_k = trace(P_k), k = 0..4.
// Then 12 power iterations + Rayleigh on P_5 (~A^32 normalized), unwind:
// lam_k = t_k * sqrt(lam_{k+1});  sigma = sqrt(lam_0).
// Template specialization -> fully unrolled loops. 256 threads, 3 blocks.
// =============================================================================
template<int R, int C>
__device__ __forceinline__ void sigma_body(const float* __restrict__ W,
                                           float* A, float* Bm, float* v,
                                           float* sT, float* red, int outIdx) {
    const int t = threadIdx.x;   // 256

    // Gram: A = W W^T (row stride 64)
    for (int idx = t; idx < R * R; idx += 256) {
        int i = idx / R, j = idx % R;
        float a0 = 0.f, a1 = 0.f, a2 = 0.f, a3 = 0.f;
        #pragma unroll
        for (int k = 0; k < C; k += 4) {
            a0 += W[i * C + k]     * W[j * C + k];
            a1 += W[i * C + k + 1] * W[j * C + k + 1];
            a2 += W[i * C + k + 2] * W[j * C + k + 2];
            a3 += W[i * C + k + 3] * W[j * C + k + 3];
        }
        A[i * 64 + j] = (a0 + a1) + (a2 + a3);
    }
    __syncthreads();
    // trace(P_0)
    if (t < 32) {
        float s = 0.f;
        for (int k = t; k < R; k += 32) s += A[k * 64 + k];
        #pragma unroll
        for (int o = 16; o > 0; o >>= 1) s += __shfl_xor_sync(0xffffffffu, s, o);
        if (t == 0) sT[0] = s;
    }
    __syncthreads();

    // 5 squarings with fused normalization
    float* src = A;
    float* dst = Bm;
    #pragma unroll
    for (int sq = 0; sq < 5; sq++) {
        const float invt = 1.0f / sT[sq];
        const float f = invt * invt;
        for (int idx = t; idx < R * R; idx += 256) {
            int i = idx / R, j = idx % R;
            float a0 = 0.f, a1 = 0.f, a2 = 0.f, a3 = 0.f;
            #pragma unroll
            for (int k = 0; k < R; k += 4) {
                a0 += src[i * 64 + k]     * src[k * 64 + j];
                a1 += src[i * 64 + k + 1] * src[(k + 1) * 64 + j];
                a2 += src[i * 64 + k + 2] * src[(k + 2) * 64 + j];
                a3 += src[i * 64 + k + 3] * src[(k + 3) * 64 + j];
            }
            dst[i * 64 + j] = ((a0 + a1) + (a2 + a3)) * f;
        }
        __syncthreads();
        if (t < 32) {
            float s = 0.f;
            for (int k = t; k < R; k += 32) s += dst[k * 64 + k];
            #pragma unroll
            for (int o = 16; o > 0; o >>= 1) s += __shfl_xor_sync(0xffffffffu, s, o);
            if (t == 0) sT[sq + 1] = s;
        }
        __syncthreads();
        float* tmp = src; src = dst; dst = tmp;
    }
    // P_5 now in src.

    if (t < R) v[t] = 1.0f;
    __syncthreads();

    #pragma unroll 1
    for (int it = 0; it < 12; it++) {
        float wi = 0.f;
        if (t < R) {
            float w0 = 0.f, w1 = 0.f, w2 = 0.f, w3 = 0.f;
            #pragma unroll
            for (int k = 0; k < R; k += 4) {
                w0 += src[t * 64 + k]     * v[k];
                w1 += src[t * 64 + k + 1] * v[k + 1];
                w2 += src[t * 64 + k + 2] * v[k + 2];
                w3 += src[t * 64 + k + 3] * v[k + 3];
            }
            wi = (w0 + w1) + (w2 + w3);
        }
        float s2 = (t < 64) ? wi * wi : 0.f;
        #pragma unroll
        for (int o = 16; o > 0; o >>= 1) s2 += __shfl_xor_sync(0xffffffffu, s2, o);
        if (t < 64 && (t & 31) == 0) red[t >> 5] = s2;
        __syncthreads();
        float inv = rsqrtf(red[0] + red[1]);
        if (t < R) v[t] = wi * inv;
        __syncthreads();
    }

    // Rayleigh quotient mu = v^T P_5 v (v unit)
    float wi = 0.f;
    if (t < R) {
        #pragma unroll
        for (int k = 0; k < R; k++) wi += src[t * 64 + k] * v[k];
        wi *= v[t];
    }
    if (t >= 64) wi = 0.f;
    #pragma unroll
    for (int o = 16; o > 0; o >>= 1) wi += __shfl_xor_sync(0xffffffffu, wi, o);
    if (t < 64 && (t & 31) == 0) red[t >> 5] = wi;
    __syncthreads();
    if (t == 0) {
        float mu = red[0] + red[1];              // lam(P_5)
        #pragma unroll
        for (int k = 4; k >= 0; k--) mu = sT[k] * sqrtf(mu);
        g_sig_inv[outIdx] = rsqrtf(mu);          // 1/sigma = lam(A)^(-1/2)
    }
}

__global__ void __launch_bounds__(256) sigma_kernel(const float* __restrict__ Wq,
                                                    const float* __restrict__ Wk,
                                                    const float* __restrict__ Wv) {
    __shared__ float A[64 * 64];
    __shared__ float Bm[64 * 64];
    __shared__ float v[64];
    __shared__ float sT[8];
    __shared__ float red[2];

    if (blockIdx.x == 0)      sigma_body<NC8, NC>(Wq, A, Bm, v, sT, red, 0);
    else if (blockIdx.x == 1) sigma_body<NC8, NC>(Wk, A, Bm, v, sT, red, 1);
    else                      sigma_body<NC,  NC>(Wv, A, Bm, v, sT, red, 2);
}

// =============================================================================
// Kernel 2: projections (unchanged).
// =============================================================================
__global__ void __launch_bounds__(128) proj_kernel(
    const float* __restrict__ x,
    const float* __restrict__ Wq, const float* __restrict__ bq,
    const float* __restrict__ Wk, const float* __restrict__ bk,
    const float* __restrict__ Wv, const float* __restrict__ bv) {

    __shared__ float Wvs[64 * 64];
    __shared__ float Wqs[8 * 64];
    __shared__ float Wks[8 * 64];
    __shared__ float bqs[8], bks[8], bvs[64];

    const int blk = blockIdx.x;
    const int b   = blk / QTILES;
    const int n0  = (blk % QTILES) * 128;
    const int t   = threadIdx.x;

    const float siq = g_sig_inv[0], sik = g_sig_inv[1], siv = g_sig_inv[2];
    for (int i = t; i < 64 * 64; i += 128) Wvs[i] = Wv[i] * siv;
    for (int i = t; i < 512; i += 128) { Wqs[i] = Wq[i] * siq; Wks[i] = Wk[i] * sik; }
    if (t < 8)  { bqs[t] = bq[t]; bks[t] = bk[t]; }
    if (t < 64) bvs[t] = bv[t];
    __syncthreads();

    const int n = n0 + t;
    float xr[64];
    #pragma unroll
    for (int cc = 0; cc < 64; cc++)
        xr[cc] = x[((size_t)b * NC + cc) * N_TOK + n];

    float* fo = &g_fT[((size_t)b * N_TOK + n) * NC8];
    float* go = &g_gT[((size_t)b * N_TOK + n) * NC8];
    float* ho = &g_hT[((size_t)b * N_TOK + n) * NC];

    for (int o = 0; o < 8; o++) {
        float a1 = bqs[o], a2 = bks[o];
        #pragma unroll
        for (int cc = 0; cc < 64; cc++) {
            a1 += Wqs[o * 64 + cc] * xr[cc];
            a2 += Wks[o * 64 + cc] * xr[cc];
        }
        fo[o] = a1;
        go[o] = a2;
    }
    for (int o = 0; o < 64; o++) {
        float a1 = bvs[o];
        #pragma unroll
        for (int cc = 0; cc < 64; cc++) a1 += Wvs[o * 64 + cc] * xr[cc];
        ho[o] = a1;
    }
}

// =============================================================================
// Kernel 3: flash attention, 2 queries/thread, 4-way key split,
// 64-key tiles, double-buffered smem with register prefetch:
// [STS cur][bar][LDG next][compute cur] -> one barrier per tile, load latency
// hidden under ~1024 FFMA2 of compute.
// grid = 144 blocks (b, 128-query tile), 256 threads.
// =============================================================================
__global__ void __launch_bounds__(256, 1) attn_kernel(
    const float* __restrict__ x,
    const float* __restrict__ gamma,
    float* __restrict__ out) {

    // pool layout (f4): [HS0 1024][FS0 128][HS1 1024][FS1 128] = 2304 f4 (36.8KB)
    __shared__ float4 s_pool[2304];
    __shared__ float  mrg_m[128], mrg_l[128];

    const int blk     = blockIdx.x;
    const int b       = blk / QTILES;
    const int j0      = (blk % QTILES) * 128;
    const int t       = threadIdx.x;
    const int qp      = t & 63;
    const int quarter = t >> 6;
    const int jA      = j0 + qp * 2;

    const float4* gA = (const float4*)&g_gT[((size_t)b * N_TOK + jA) * NC8];
    const float4 qa0 = gA[0], qa1 = gA[1];
    const float4 qb0 = gA[2], qb1 = gA[3];

    unsigned long long oA[32], oB[32];
    #pragma unroll
    for (int i = 0; i < 32; i++) { oA[i] = 0ull; oB[i] = 0ull; }
    float ma = -1e30f, la = 0.f, mb = -1e30f, lb = 0.f;

    const float4* fbase = (const float4*)&g_fT[(size_t)b * N_TOK * NC8];
    const float4* hbase = (const float4*)&g_hT[(size_t)b * N_TOK * NC];

    // prefetch tile 0
    float4 hp0 = hbase[t];
    float4 hp1 = hbase[t + 256];
    float4 hp2 = hbase[t + 512];
    float4 hp3 = hbase[t + 768];
    float4 fp;
    if (t < 128) fp = fbase[t];

    for (int it = 0; it < NKT; it++) {
        float4* const HS = s_pool + (it & 1) * 1152;
        float4* const FS = HS + 1024;
        HS[t]       = hp0;
        HS[t + 256] = hp1;
        HS[t + 512] = hp2;
        HS[t + 768] = hp3;
        if (t < 128) FS[t] = fp;
        __syncthreads();
        if (it + 1 < NKT) {
            const int nb = (it + 1) * 1024;
            hp0 = hbase[nb + t];
            hp1 = hbase[nb + t + 256];
            hp2 = hbase[nb + t + 512];
            hp3 = hbase[nb + t + 768];
            if (t < 128) fp = fbase[(it + 1) * 128 + t];
        }

        const int r0 = quarter * 16;
        #pragma unroll
        for (int kc = 0; kc < 16; kc += 8) {
            float pA[8], pB[8];
            {
                float sA[8], sB[8];
                #pragma unroll
                for (int kk = 0; kk < 8; kk++) {
                    float4 fa = FS[(r0 + kc + kk) * 2];
                    float4 fb = FS[(r0 + kc + kk) * 2 + 1];
                    sA[kk] = fa.x * qa0.x + fa.y * qa0.y + fa.z * qa0.z + fa.w * qa0.w
                           + fb.x * qa1.x + fb.y * qa1.y + fb.z * qa1.z + fb.w * qa1.w;
                    sB[kk] = fa.x * qb0.x + fa.y * qb0.y + fa.z * qb0.z + fa.w * qb0.w
                           + fb.x * qb1.x + fb.y * qb1.y + fb.z * qb1.z + fb.w * qb1.w;
                }
                float mtA = sA[0], mtB = sB[0];
                #pragma unroll
                for (int kk = 1; kk < 8; kk++) {
                    mtA = fmaxf(mtA, sA[kk]);
                    mtB = fmaxf(mtB, sB[kk]);
                }
                if (mtA > ma) {
                    float sc = __expf(ma - mtA);
                    la *= sc;
                    unsigned long long sc2 = pk2(sc, sc);
                    #pragma unroll
                    for (int i = 0; i < 32; i++) mul2(oA[i], sc2);
                    ma = mtA;
                }
                if (mtB > mb) {
                    float sc = __expf(mb - mtB);
                    lb *= sc;
                    unsigned long long sc2 = pk2(sc, sc);
                    #pragma unroll
                    for (int i = 0; i < 32; i++) mul2(oB[i], sc2);
                    mb = mtB;
                }
                float lsA = 0.f, lsB = 0.f;
                #pragma unroll
                for (int kk = 0; kk < 8; kk++) {
                    pA[kk] = __expf(sA[kk] - ma); lsA += pA[kk];
                    pB[kk] = __expf(sB[kk] - mb); lsB += pB[kk];
                }
                la += lsA; lb += lsB;
            }
            #pragma unroll
            for (int kk = 0; kk < 8; kk++) {
                unsigned long long ppA = pk2(pA[kk], pA[kk]);
                unsigned long long ppB = pk2(pB[kk], pB[kk]);
                const ulonglong2* hrow = (const ulonglong2*)(HS + (r0 + kc + kk) * 16);
                #pragma unroll
                for (int c4 = 0; c4 < 16; c4++) {
                    ulonglong2 hv = hrow[c4];
                    fma2(oA[c4 * 2],     hv.x, ppA);
                    fma2(oA[c4 * 2 + 1], hv.y, ppA);
                    fma2(oB[c4 * 2],     hv.x, ppB);
                    fma2(oB[c4 * 2 + 1], hv.y, ppB);
                }
            }
        }
    }

    // merge quarters 1..3 into quarter 0 (3 sequential smem rounds)
    unsigned long long* mo = (unsigned long long*)s_pool;   // 128q x 32 u64 = 32KB
    for (int round = 1; round < 4; round++) {
        __syncthreads();
        if (quarter == round) {
            mrg_m[qp * 2]     = ma; mrg_l[qp * 2]     = la;
            mrg_m[qp * 2 + 1] = mb; mrg_l[qp * 2 + 1] = lb;
            #pragma unroll
            for (int i = 0; i < 32; i++) {
                mo[(qp * 2) * 32 + i]     = oA[i];
                mo[(qp * 2 + 1) * 32 + i] = oB[i];
            }
        }
        __syncthreads();
        if (quarter == 0) {
            {
                float m1 = mrg_m[qp * 2], l1 = mrg_l[qp * 2];
                float mn = fmaxf(ma, m1);
                float s0 = __expf(ma - mn), s1 = __expf(m1 - mn);
                la = la * s0 + l1 * s1;
                ma = mn;
                unsigned long long s02 = pk2(s0, s0), s12 = pk2(s1, s1);
                #pragma unroll
                for (int i = 0; i < 32; i++) {
                    mul2(oA[i], s02);
                    fma2(oA[i], mo[(qp * 2) * 32 + i], s12);
                }
            }
            {
                float m1 = mrg_m[qp * 2 + 1], l1 = mrg_l[qp * 2 + 1];
                float mn = fmaxf(mb, m1);
                float s0 = __expf(mb - mn), s1 = __expf(m1 - mn);
                lb = lb * s0 + l1 * s1;
                mb = mn;
                unsigned long long s02 = pk2(s0, s0), s12 = pk2(s1, s1);
                #pragma unroll
                for (int i = 0; i < 32; i++) {
                    mul2(oB[i], s02);
                    fma2(oB[i], mo[(qp * 2 + 1) * 32 + i], s12);
                }
            }
        }
    }
    __syncthreads();

    if (quarter == 0) {
        const float ga  = gamma[0];
        const float gsA = ga / la, gsB = ga / lb;
        const size_t base = (size_t)b * NC * N_TOK + jA;
        const float* xp = x + base;
        float* op = out + base;
        #pragma unroll
        for (int i = 0; i < 32; i++) {
            float a0, a1, b0, b1;
            upk2(oA[i], a0, a1);
            upk2(oB[i], b0, b1);
            const size_t c0 = (size_t)(2 * i) * N_TOK;
            const size_t c1 = c0 + N_TOK;
            op[c0]     = a0 * gsA + xp[c0];
            op[c0 + 1] = b0 * gsB + xp[c0 + 1];
            op[c1]     = a1 * gsA + xp[c1];
            op[c1 + 1] = b1 * gsB + xp[c1 + 1];
        }
    }
}

// =============================================================================
extern "C" void kernel_launch(void* const* d_in, const int* in_sizes, int n_in,
                              void* d_out, int out_size) {
    const float* x     = (const float*)d_in[0];
    const float* Wq    = (const float*)d_in[1];
    const float* bq    = (const float*)d_in[2];
    const float* Wk    = (const float*)d_in[3];
    const float* bk    = (const float*)d_in[4];
    const float* Wv    = (const float*)d_in[5];
    const float* bv    = (const float*)d_in[6];
    const float* gamma = (const float*)d_in[7];
    float* out = (float*)d_out;

    sigma_kernel<<<3, 256>>>(Wq, Wk, Wv);
    proj_kernel<<<NBATCH * QTILES, 128>>>(x, Wq, bq, Wk, bk, Wv, bv);
    attn_kernel<<<NBATCH * QTILES, 256>>>(x, gamma, out);
}

// round 14
// speedup vs baseline: 1.8215x; 1.8215x over previous
#include <cuda_runtime.h>
#include <cuda_bf16.h>

// Problem constants
#define N_TOK   9216        // H*W
#define NBATCH  2
#define NC      64
#define NC8     8
#define QTILES  72          // query tiles of 128
#define NKT     144         // key tiles of 64
#define LOG2E   1.4426950408889634f

// ---------------- scratch (static device allocation: allowed) ----------------
__device__ float g_sig_inv[3];
__device__ unsigned int g_maxf_bits[NBATCH];                 // max_i |f_i| per batch (bits)
__device__ float g_fT[NBATCH * N_TOK * NC8];                 // keys,    [b][n][8]
__device__ float g_gT[NBATCH * N_TOK * NC8];                 // queries, [b][n][8]
__device__ __nv_bfloat16 g_hHi[NBATCH * NC * N_TOK];         // values hi, [b][c][n]
__device__ __nv_bfloat16 g_hLo[NBATCH * NC * N_TOK];         // values lo, [b][c][n]

// ---------------- packed f32x2 helpers ----------------
__device__ __forceinline__ unsigned long long pk2(float a, float b) {
    unsigned long long r;
    asm("mov.b64 %0, {%1, %2};" : "=l"(r) : "f"(a), "f"(b));
    return r;
}
__device__ __forceinline__ void upk2(unsigned long long v, float& a, float& b) {
    asm("mov.b64 {%0, %1}, %2;" : "=f"(a), "=f"(b) : "l"(v));
}
__device__ __forceinline__ void fma2(unsigned long long& d,
                                     unsigned long long a, unsigned long long b) {
    asm("fma.rn.f32x2 %0, %1, %2, %0;" : "+l"(d) : "l"(a), "l"(b));
}
__device__ __forceinline__ float ex2(float x) {
    float r; asm("ex2.approx.ftz.f32 %0, %1;" : "=f"(r) : "f"(x)); return r;
}

// ---------------- base-ISA tensor helpers (sm_80+: ldmatrix + mma.sync) -------
__device__ __forceinline__ unsigned smem_u32(const void* p) {
    unsigned a;
    asm("{ .reg .u64 t; cvta.to.shared.u64 t, %1; cvt.u32.u64 %0, t; }" : "=r"(a) : "l"(p));
    return a;
}
__device__ __forceinline__ void ldsm4(unsigned& r0, unsigned& r1,
                                      unsigned& r2, unsigned& r3, unsigned addr) {
    asm volatile("ldmatrix.sync.aligned.m8n8.x4.shared.b16 {%0,%1,%2,%3}, [%4];"
                 : "=r"(r0), "=r"(r1), "=r"(r2), "=r"(r3) : "r"(addr));
}
__device__ __forceinline__ void mma_bf16(float* c, const unsigned* a,
                                         unsigned b0, unsigned b1) {
    asm volatile(
        "mma.sync.aligned.m16n8k16.row.col.f32.bf16.bf16.f32 "
        "{%0,%1,%2,%3}, {%4,%5,%6,%7}, {%8,%9}, {%0,%1,%2,%3};"
        : "+f"(c[0]), "+f"(c[1]), "+f"(c[2]), "+f"(c[3])
        : "r"(a[0]), "r"(a[1]), "r"(a[2]), "r"(a[3]), "r"(b0), "r"(b1));
}
// pack {low=lo_elem, high=hi_elem} as bf16x2 (round-to-nearest both)
__device__ __forceinline__ unsigned cvt2(float hi_elem, float lo_elem) {
    unsigned r;
    asm("cvt.rn.bf16x2.f32 %0, %1, %2;" : "=r"(r) : "f"(hi_elem), "f"(lo_elem));
    return r;
}

// SMEM layout (dynamic). Stride 144B (72 bf16) for all matrix tiles.
#define BUFS     57344
#define S_PHI(b) ((b)*BUFS)
#define S_PLO(b) ((b)*BUFS + 18432)
#define S_HHI(b) ((b)*BUFS + 36864)
#define S_HLO(b) ((b)*BUFS + 46080)
#define S_FT(b)  ((b)*BUFS + 55296)
#define S_LP     (2*BUFS)
#define SMEM_TOTAL (S_LP + 512*4 + 64)

// =============================================================================
// Kernel 1: spectral norms (trace-normalized repeated squaring)
// =============================================================================
template<int R, int C>
__device__ __forceinline__ void sigma_body(const float* __restrict__ W,
                                           float* A, float* Bm, float* v,
                                           float* sT, float* red, int outIdx) {
    const int t = threadIdx.x;

    for (int idx = t; idx < R * R; idx += 256) {
        int i = idx / R, j = idx % R;
        float a0 = 0.f, a1 = 0.f, a2 = 0.f, a3 = 0.f;
        #pragma unroll
        for (int k = 0; k < C; k += 4) {
            a0 += W[i * C + k]     * W[j * C + k];
            a1 += W[i * C + k + 1] * W[j * C + k + 1];
            a2 += W[i * C + k + 2] * W[j * C + k + 2];
            a3 += W[i * C + k + 3] * W[j * C + k + 3];
        }
        A[i * 64 + j] = (a0 + a1) + (a2 + a3);
    }
    __syncthreads();
    if (t < 32) {
        float s = 0.f;
        for (int k = t; k < R; k += 32) s += A[k * 64 + k];
        #pragma unroll
        for (int o = 16; o > 0; o >>= 1) s += __shfl_xor_sync(0xffffffffu, s, o);
        if (t == 0) sT[0] = s;
    }
    __syncthreads();

    float* src = A;
    float* dst = Bm;
    #pragma unroll
    for (int sq = 0; sq < 5; sq++) {
        const float invt = 1.0f / sT[sq];
        const float f = invt * invt;
        for (int idx = t; idx < R * R; idx += 256) {
            int i = idx / R, j = idx % R;
            float a0 = 0.f, a1 = 0.f, a2 = 0.f, a3 = 0.f;
            #pragma unroll
            for (int k = 0; k < R; k += 4) {
                a0 += src[i * 64 + k]     * src[k * 64 + j];
                a1 += src[i * 64 + k + 1] * src[(k + 1) * 64 + j];
                a2 += src[i * 64 + k + 2] * src[(k + 2) * 64 + j];
                a3 += src[i * 64 + k + 3] * src[(k + 3) * 64 + j];
            }
            dst[i * 64 + j] = ((a0 + a1) + (a2 + a3)) * f;
        }
        __syncthreads();
        if (t < 32) {
            float s = 0.f;
            for (int k = t; k < R; k += 32) s += dst[k * 64 + k];
            #pragma unroll
            for (int o = 16; o > 0; o >>= 1) s += __shfl_xor_sync(0xffffffffu, s, o);
            if (t == 0) sT[sq + 1] = s;
        }
        __syncthreads();
        float* tmp = src; src = dst; dst = tmp;
    }

    if (t < R) v[t] = 1.0f;
    __syncthreads();

    #pragma unroll 1
    for (int it = 0; it < 12; it++) {
        float wi = 0.f;
        if (t < R) {
            float w0 = 0.f, w1 = 0.f, w2 = 0.f, w3 = 0.f;
            #pragma unroll
            for (int k = 0; k < R; k += 4) {
                w0 += src[t * 64 + k]     * v[k];
                w1 += src[t * 64 + k + 1] * v[k + 1];
                w2 += src[t * 64 + k + 2] * v[k + 2];
                w3 += src[t * 64 + k + 3] * v[k + 3];
            }
            wi = (w0 + w1) + (w2 + w3);
        }
        float s2 = (t < 64) ? wi * wi : 0.f;
        #pragma unroll
        for (int o = 16; o > 0; o >>= 1) s2 += __shfl_xor_sync(0xffffffffu, s2, o);
        if (t < 64 && (t & 31) == 0) red[t >> 5] = s2;
        __syncthreads();
        float inv = rsqrtf(red[0] + red[1]);
        if (t < R) v[t] = wi * inv;
        __syncthreads();
    }

    float wi = 0.f;
    if (t < R) {
        #pragma unroll
        for (int k = 0; k < R; k++) wi += src[t * 64 + k] * v[k];
        wi *= v[t];
    }
    if (t >= 64) wi = 0.f;
    #pragma unroll
    for (int o = 16; o > 0; o >>= 1) wi += __shfl_xor_sync(0xffffffffu, wi, o);
    if (t < 64 && (t & 31) == 0) red[t >> 5] = wi;
    __syncthreads();
    if (t == 0) {
        float mu = red[0] + red[1];
        #pragma unroll
        for (int k = 4; k >= 0; k--) mu = sT[k] * sqrtf(mu);
        g_sig_inv[outIdx] = rsqrtf(mu);
    }
}

__global__ void __launch_bounds__(256) sigma_kernel(const float* __restrict__ Wq,
                                                    const float* __restrict__ Wk,
                                                    const float* __restrict__ Wv) {
    __shared__ float A[64 * 64];
    __shared__ float Bm[64 * 64];
    __shared__ float v[64];
    __shared__ float sT[8];
    __shared__ float red[2];

    if (blockIdx.x == 0 && threadIdx.x == 0) {
        g_maxf_bits[0] = 0u;
        g_maxf_bits[1] = 0u;
    }
    if (blockIdx.x == 0)      sigma_body<NC8, NC>(Wq, A, Bm, v, sT, red, 0);
    else if (blockIdx.x == 1) sigma_body<NC8, NC>(Wk, A, Bm, v, sT, red, 1);
    else                      sigma_body<NC,  NC>(Wv, A, Bm, v, sT, red, 2);
}

// =============================================================================
// Kernel 2: projections. f,g fp32 token-major; h split to bf16 hi/lo planes
// channel-major [b][c][n]; per-batch max|f| via atomicMax.
// =============================================================================
__global__ void __launch_bounds__(128) proj_kernel(
    const float* __restrict__ x,
    const float* __restrict__ Wq, const float* __restrict__ bq,
    const float* __restrict__ Wk, const float* __restrict__ bk,
    const float* __restrict__ Wv, const float* __restrict__ bv) {

    __shared__ float Wvs[64 * 64];
    __shared__ float Wqs[8 * 64];
    __shared__ float Wks[8 * 64];
    __shared__ float bqs[8], bks[8], bvs[64];
    __shared__ float rmax[4];

    const int blk = blockIdx.x;
    const int b   = blk / QTILES;
    const int n0  = (blk % QTILES) * 128;
    const int t   = threadIdx.x;

    const float siq = g_sig_inv[0], sik = g_sig_inv[1], siv = g_sig_inv[2];
    for (int i = t; i < 64 * 64; i += 128) Wvs[i] = Wv[i] * siv;
    for (int i = t; i < 512; i += 128) { Wqs[i] = Wq[i] * siq; Wks[i] = Wk[i] * sik; }
    if (t < 8)  { bqs[t] = bq[t]; bks[t] = bk[t]; }
    if (t < 64) bvs[t] = bv[t];
    __syncthreads();

    const int n = n0 + t;
    float xr[64];
    #pragma unroll
    for (int cc = 0; cc < 64; cc++)
        xr[cc] = x[((size_t)b * NC + cc) * N_TOK + n];

    float* fo = &g_fT[((size_t)b * N_TOK + n) * NC8];
    float* go = &g_gT[((size_t)b * N_TOK + n) * NC8];

    float nf = 0.f;
    for (int o = 0; o < 8; o++) {
        float a1 = bqs[o], a2 = bks[o];
        #pragma unroll
        for (int cc = 0; cc < 64; cc++) {
            a1 += Wqs[o * 64 + cc] * xr[cc];
            a2 += Wks[o * 64 + cc] * xr[cc];
        }
        fo[o] = a1;
        go[o] = a2;
        nf += a1 * a1;
    }
    float normf = sqrtf(nf);
    #pragma unroll
    for (int o = 16; o > 0; o >>= 1)
        normf = fmaxf(normf, __shfl_xor_sync(0xffffffffu, normf, o));
    if ((t & 31) == 0) rmax[t >> 5] = normf;
    __syncthreads();
    if (t == 0) {
        float m = fmaxf(fmaxf(rmax[0], rmax[1]), fmaxf(rmax[2], rmax[3]));
        atomicMax(&g_maxf_bits[b], __float_as_uint(m));
    }

    for (int o = 0; o < 64; o++) {
        float a1 = bvs[o];
        #pragma unroll
        for (int cc = 0; cc < 64; cc++) a1 += Wvs[o * 64 + cc] * xr[cc];
        __nv_bfloat16 hi = __float2bfloat16(a1);
        float lo = a1 - __bfloat162float(hi);
        const size_t off = ((size_t)b * NC + o) * N_TOK + n;
        g_hHi[off] = hi;
        g_hLo[off] = __float2bfloat16(lo);
    }
}

// =============================================================================
// Kernel 3: HMMA flash attention with bound-based softmax.
// 144 blocks (b, 128-query tile), 256 threads = 8 warps.
// Warp w owns query rows 16w..16w+15 x all 64 channels in fp32 mma.sync
// accumulators, accumulated over 144 key tiles (no rescale thanks to bound).
// Per tile: scalar QK + exp2 -> P bf16 hi/lo STS -> ldmatrix + 96 HMMA/warp
// (Phi*Hhi + Phi*Hlo + Plo*Hhi). H staged channel-major [64c x 64k] so BOTH
// A and B fragments use non-trans ldmatrix.x4. Double-buffered smem.
// =============================================================================
__global__ void __launch_bounds__(256, 1)
attn_kernel(const float* __restrict__ x,
            const float* __restrict__ gamma,
            float* __restrict__ out) {

    extern __shared__ char sm_[];
    const unsigned sbase = smem_u32(sm_);

    const int t       = threadIdx.x;
    const int wid     = t >> 5;
    const int lane    = t & 31;
    const int blk     = blockIdx.x;
    const int b       = blk / QTILES;
    const int j0      = (blk % QTILES) * 128;
    const int qp      = t & 63;
    const int quarter = t >> 6;
    const int jA      = j0 + 2 * qp;

    // queries (premultiplied by log2e), per-query softmax bound
    const float* gp = &g_gT[((size_t)b * N_TOK + jA) * NC8];
    float qa[8], qb[8], na = 0.f, nb = 0.f;
    #pragma unroll
    for (int c = 0; c < 8; c++) {
        float va = gp[c], vb = gp[8 + c];
        na += va * va; nb += vb * vb;
        qa[c] = va * LOG2E; qb[c] = vb * LOG2E;
    }
    const float maxF = __uint_as_float(g_maxf_bits[b]);
    const float mbA = sqrtf(na) * maxF * LOG2E;
    const float mbB = sqrtf(nb) * maxF * LOG2E;
    unsigned long long qd[8];
    #pragma unroll
    for (int c = 0; c < 8; c++) qd[c] = pk2(qa[c], qb[c]);
    const unsigned long long mseed = pk2(-mbA, -mbB);

    const float4* fbase = (const float4*)&g_fT[(size_t)b * N_TOK * NC8];
    const size_t  hbase = (size_t)b * NC * N_TOK;

    // H/F prefetch: thread covers (ch0, 8 keys) and (ch1, 8 keys)
    const int ch0 = t >> 3,         cn0 = t & 7;
    const int ch1 = (t + 256) >> 3, cn1 = (t + 256) & 7;
    uint4 vh0, vl0, vh1, vl1;
    float4 fpre;
    {
        const size_t r0 = hbase + (size_t)ch0 * N_TOK + cn0 * 8;
        const size_t r1 = hbase + (size_t)ch1 * N_TOK + cn1 * 8;
        vh0 = *(const uint4*)&g_hHi[r0];
        vl0 = *(const uint4*)&g_hLo[r0];
        vh1 = *(const uint4*)&g_hHi[r1];
        vl1 = *(const uint4*)&g_hLo[r1];
        if (t < 128) fpre = fbase[t];
    }
    const unsigned hoff0 = (unsigned)(ch0 * 144 + cn0 * 16);
    const unsigned hoff1 = (unsigned)(ch1 * 144 + cn1 * 16);

    // mma accumulators: 8 channel-tiles x {c0..c3}
    float Cacc[8][4];
    #pragma unroll
    for (int i = 0; i < 8; i++)
        #pragma unroll
        for (int k = 0; k < 4; k++) Cacc[i][k] = 0.f;
    float lA = 0.f, lB = 0.f;

    // per-lane ldmatrix address components (non-trans x4)
    const int sel     = lane >> 3;
    const unsigned aoff = (unsigned)((16 * wid + (lane & 7) + (sel & 1) * 8) * 144
                                     + ((sel >> 1) & 1) * 16);
    const int brow_off  = (lane & 7) + ((sel >> 1) & 1) * 8;
    const unsigned bco  = (unsigned)((sel & 1) * 16);

    for (int tile = 0; tile < NKT; tile++) {
        const int buf = tile & 1;

        // stage H hi/lo + F from prefetch registers
        *(uint4*)(sm_ + S_HHI(buf) + hoff0) = vh0;
        *(uint4*)(sm_ + S_HLO(buf) + hoff0) = vl0;
        *(uint4*)(sm_ + S_HHI(buf) + hoff1) = vh1;
        *(uint4*)(sm_ + S_HLO(buf) + hoff1) = vl1;
        if (t < 128) ((float4*)(sm_ + S_FT(buf)))[t] = fpre;
        __syncthreads();

        // prefetch next tile
        if (tile + 1 < NKT) {
            const int k0n = (tile + 1) * 64;
            const size_t r0 = hbase + (size_t)ch0 * N_TOK + k0n + cn0 * 8;
            const size_t r1 = hbase + (size_t)ch1 * N_TOK + k0n + cn1 * 8;
            vh0 = *(const uint4*)&g_hHi[r0];
            vl0 = *(const uint4*)&g_hLo[r0];
            vh1 = *(const uint4*)&g_hHi[r1];
            vl1 = *(const uint4*)&g_hLo[r1];
            if (t < 128) fpre = fbase[k0n * 2 + t];
        }

        // scalar QK + exp2 for my 2 queries x 16 keys
        const float4* FS = (const float4*)(sm_ + S_FT(buf));
        float pA[16], pB[16];
        #pragma unroll
        for (int kk = 0; kk < 16; kk++) {
            const int key = (quarter << 4) + kk;
            float4 fa = FS[key * 2];
            float4 fb = FS[key * 2 + 1];
            unsigned long long acc = mseed;
            fma2(acc, pk2(fa.x, fa.x), qd[0]);
            fma2(acc, pk2(fa.y, fa.y), qd[1]);
            fma2(acc, pk2(fa.z, fa.z), qd[2]);
            fma2(acc, pk2(fa.w, fa.w), qd[3]);
            fma2(acc, pk2(fb.x, fb.x), qd[4]);
            fma2(acc, pk2(fb.y, fb.y), qd[5]);
            fma2(acc, pk2(fb.z, fb.z), qd[6]);
            fma2(acc, pk2(fb.w, fb.w), qd[7]);
            float sa, sb; upk2(acc, sa, sb);
            pA[kk] = ex2(sa); pB[kk] = ex2(sb);
            lA += pA[kk]; lB += pB[kk];
        }

        // split bf16 hi/lo, STS into P tiles (rows 2qp, 2qp+1, keys quarter*16..)
        #pragma unroll
        for (int qsel = 0; qsel < 2; qsel++) {
            const float* p = qsel ? pB : pA;
            const unsigned rowaddr = (unsigned)((2 * qp + qsel) * 144 + quarter * 32);
            unsigned hw[8], lw[8];
            #pragma unroll
            for (int e = 0; e < 8; e++) {
                float p0 = p[2 * e], p1 = p[2 * e + 1];
                unsigned h = cvt2(p1, p0);
                float f0 = __uint_as_float(h << 16);
                float f1 = __uint_as_float(h & 0xffff0000u);
                hw[e] = h;
                lw[e] = cvt2(p1 - f1, p0 - f0);
            }
            *(uint4*)(sm_ + S_PHI(buf) + rowaddr)      = make_uint4(hw[0], hw[1], hw[2], hw[3]);
            *(uint4*)(sm_ + S_PHI(buf) + rowaddr + 16) = make_uint4(hw[4], hw[5], hw[6], hw[7]);
            *(uint4*)(sm_ + S_PLO(buf) + rowaddr)      = make_uint4(lw[0], lw[1], lw[2], lw[3]);
            *(uint4*)(sm_ + S_PLO(buf) + rowaddr + 16) = make_uint4(lw[4], lw[5], lw[6], lw[7]);
        }
        __syncthreads();

        // HMMA phase
        const unsigned phiB = sbase + S_PHI(buf);
        const unsigned ploB = sbase + S_PLO(buf);
        const unsigned hhiB = sbase + S_HHI(buf);
        const unsigned hloB = sbase + S_HLO(buf);
        #pragma unroll
        for (int kc = 0; kc < 4; kc++) {
            unsigned ah[4], al[4];
            ldsm4(ah[0], ah[1], ah[2], ah[3], phiB + aoff + kc * 32);
            ldsm4(al[0], al[1], al[2], al[3], ploB + aoff + kc * 32);
            #pragma unroll
            for (int ct = 0; ct < 4; ct++) {
                const unsigned baddr = (unsigned)((ct * 16 + brow_off) * 144) + bco + kc * 32;
                unsigned b0, b1, b2, b3;
                ldsm4(b0, b1, b2, b3, hhiB + baddr);
                mma_bf16(Cacc[2 * ct],     ah, b0, b1);
                mma_bf16(Cacc[2 * ct + 1], ah, b2, b3);
                mma_bf16(Cacc[2 * ct],     al, b0, b1);
                mma_bf16(Cacc[2 * ct + 1], al, b2, b3);
                ldsm4(b0, b1, b2, b3, hloB + baddr);
                mma_bf16(Cacc[2 * ct],     ah, b0, b1);
                mma_bf16(Cacc[2 * ct + 1], ah, b2, b3);
            }
        }
    }

    // l partials -> smem, reduce per query row
    float* lp = (float*)(sm_ + S_LP);
    lp[quarter * 128 + 2 * qp]     = lA;
    lp[quarter * 128 + 2 * qp + 1] = lB;
    __syncthreads();

    // output: warp w rows 16w+gid, 16w+8+gid; channels nt*8 + (lane&3)*2 (+1)
    const int gid  = lane >> 2;
    const int tid4 = lane & 3;
    const int r0 = 16 * wid + gid;
    const int r1 = r0 + 8;
    const float l0 = lp[r0] + lp[128 + r0] + lp[256 + r0] + lp[384 + r0];
    const float l1 = lp[r1] + lp[128 + r1] + lp[256 + r1] + lp[384 + r1];
    const float ga = gamma[0];
    const float gs0 = ga / l0, gs1 = ga / l1;
    const size_t base = (size_t)b * NC * N_TOK;
    #pragma unroll
    for (int nt = 0; nt < 8; nt++) {
        const int c = nt * 8 + tid4 * 2;
        const size_t i00 = base + (size_t)c * N_TOK + (j0 + r0);
        const size_t i01 = i00 + N_TOK;
        out[i00] = Cacc[nt][0] * gs0 + x[i00];
        out[i01] = Cacc[nt][1] * gs0 + x[i01];
        const size_t i10 = base + (size_t)c * N_TOK + (j0 + r1);
        const size_t i11 = i10 + N_TOK;
        out[i10] = Cacc[nt][2] * gs1 + x[i10];
        out[i11] = Cacc[nt][3] * gs1 + x[i11];
    }
}

// =============================================================================
extern "C" void kernel_launch(void* const* d_in, const int* in_sizes, int n_in,
                              void* d_out, int out_size) {
    const float* x     = (const float*)d_in[0];
    const float* Wq    = (const float*)d_in[1];
    const float* bq    = (const float*)d_in[2];
    const float* Wk    = (const float*)d_in[3];
    const float* bk    = (const float*)d_in[4];
    const float* Wv    = (const float*)d_in[5];
    const float* bv    = (const float*)d_in[6];
    const float* gamma = (const float*)d_in[7];
    float* out = (float*)d_out;

    cudaFuncSetAttribute(attn_kernel,
                         cudaFuncAttributeMaxDynamicSharedMemorySize, SMEM_TOTAL);

    sigma_kernel<<<3, 256>>>(Wq, Wk, Wv);
    proj_kernel<<<NBATCH * QTILES, 128>>>(x, Wq, bq, Wk, bk, Wv, bv);
    attn_kernel<<<NBATCH * QTILES, 256, SMEM_TOTAL>>>(x, gamma, out);
}